// round 9
// baseline (speedup 1.0000x reference)
#include <cuda_runtime.h>
#include <math.h>
#include <stdint.h>

#define B_ 64
#define T_ 512
#define F_ 64
#define U_ 128
#define G_ 512   // 4*U

#define RGQ 18   // weight quads (4 floats) per thread in registers
#define SGQ 14   // weight quads per thread in smem (RGQ+SGQ = 32)

// ---------------- scratch (static device memory; no allocations) ----------------
__device__ float g_mask[B_ * T_];
__device__ float g_zx[2u * B_ * T_ * G_];               // layer1 then layer2 (reused)
__device__ float g_h1[B_ * T_ * 2 * U_];
__device__ float g_h2[B_ * 2 * U_];
// packed recurrent weights, quad layout:
// g_wq[seg*65536 + (m*512 + tid)*4 + e], m = gate*8 + g, tid = u*4 + q,
// holding w[k = 32q + 4g + e][col = gate*128 + u]
__device__ float g_wq[4 * G_ * U_];

// ---------------- helpers ----------------
#define FMA2(acc, a, b) asm("fma.rn.f32x2 %0, %1, %2, %0;" : "+l"(acc) : "l"(a), "l"(b))

__device__ __forceinline__ float f32x2_sum(unsigned long long v) {
    unsigned lo, hi;
    asm("mov.b64 {%0, %1}, %2;" : "=r"(lo), "=r"(hi) : "l"(v));
    return __uint_as_float(lo) + __uint_as_float(hi);
}

// ---------------- prep: mask + weight quad-packing ----------------
__global__ void prep_kernel(const float* __restrict__ x,
                            const float* __restrict__ w1f, const float* __restrict__ w1b,
                            const float* __restrict__ w2f, const float* __restrict__ w2b) {
    int i = blockIdx.x * blockDim.x + threadIdx.x;
    if (i < B_ * T_) {
        const float4* row = (const float4*)(x + (size_t)i * F_);
        bool nz = false;
#pragma unroll
        for (int k = 0; k < F_ / 4; k++) {
            float4 v = row[k];
            nz = nz || (v.x != 0.f) || (v.y != 0.f) || (v.z != 0.f) || (v.w != 0.f);
        }
        g_mask[i] = nz ? 1.f : 0.f;
    }
    int j2 = i - B_ * T_;
    if (j2 >= 0 && j2 < 4 * G_ * U_) {
        int w = j2 >> 16;
        int r = j2 & 65535;
        int k = r >> 9;            // 0..127
        int col = r & 511;         // 0..511
        const float* src = (w == 0) ? w1f : (w == 1) ? w1b : (w == 2) ? w2f : w2b;
        int u = col & 127, gate = col >> 7;
        int q = k >> 5, g = (k >> 2) & 7, e = k & 3;
        int tid2 = u * 4 + q;
        int m = gate * 8 + g;
        g_wq[w * 65536 + (m * 512 + tid2) * 4 + e] = src[r];
    }
}

// ---------------- tiled fp32 GEMM with bias: dup-A f32x2 (bit-identical to FFMA) ----------------
__global__ __launch_bounds__(256) void sgemm_bias(
    const float* __restrict__ Aext, int useH1,
    const float* __restrict__ W, const float* __restrict__ bias,
    int dirOff, int M, int N, int K) {
    __shared__ __align__(16) float Ad[16][264];   // duplicated A: col m*2{+0,+1} = a[m]
    __shared__ __align__(16) float Bs[16][128];
    const float* A = useH1 ? g_h1 : Aext;
    float* C = g_zx + (size_t)dirOff * B_ * T_ * G_;

    int tid = threadIdx.x;
    int nBase = blockIdx.x * 128;
    int mBase = blockIdx.y * 128;
    int tx = tid & 15, ty = tid >> 4;

    unsigned long long acc[8][4];
#pragma unroll
    for (int i = 0; i < 8; i++)
#pragma unroll
        for (int j = 0; j < 4; j++) acc[i][j] = 0ull;

    for (int k0 = 0; k0 < K; k0 += 16) {
#pragma unroll
        for (int s = 0; s < 2; s++) {
            int slot = tid + s * 256;
            int row = slot >> 2, c4 = slot & 3;
            float4 v = *(const float4*)(A + (size_t)(mBase + row) * K + k0 + c4 * 4);
            Ad[c4 * 4 + 0][row * 2] = v.x; Ad[c4 * 4 + 0][row * 2 + 1] = v.x;
            Ad[c4 * 4 + 1][row * 2] = v.y; Ad[c4 * 4 + 1][row * 2 + 1] = v.y;
            Ad[c4 * 4 + 2][row * 2] = v.z; Ad[c4 * 4 + 2][row * 2 + 1] = v.z;
            Ad[c4 * 4 + 3][row * 2] = v.w; Ad[c4 * 4 + 3][row * 2 + 1] = v.w;
        }
#pragma unroll
        for (int s = 0; s < 2; s++) {
            int slot = tid + s * 256;
            int row = slot >> 5, c4 = slot & 31;
            *(float4*)(&Bs[row][c4 * 4]) =
                *(const float4*)(W + (size_t)(k0 + row) * N + nBase + c4 * 4);
        }
        __syncthreads();
#pragma unroll
        for (int k = 0; k < 16; k++) {
            ulonglong2 A01 = *(const ulonglong2*)&Ad[k][ty * 16];
            ulonglong2 A23 = *(const ulonglong2*)&Ad[k][ty * 16 + 4];
            ulonglong2 A45 = *(const ulonglong2*)&Ad[k][ty * 16 + 8];
            ulonglong2 A67 = *(const ulonglong2*)&Ad[k][ty * 16 + 12];
            ulonglong2 B03 = *(const ulonglong2*)&Bs[k][tx * 8];
            ulonglong2 B47 = *(const ulonglong2*)&Bs[k][tx * 8 + 4];
            FMA2(acc[0][0], A01.x, B03.x); FMA2(acc[0][1], A01.x, B03.y);
            FMA2(acc[0][2], A01.x, B47.x); FMA2(acc[0][3], A01.x, B47.y);
            FMA2(acc[1][0], A01.y, B03.x); FMA2(acc[1][1], A01.y, B03.y);
            FMA2(acc[1][2], A01.y, B47.x); FMA2(acc[1][3], A01.y, B47.y);
            FMA2(acc[2][0], A23.x, B03.x); FMA2(acc[2][1], A23.x, B03.y);
            FMA2(acc[2][2], A23.x, B47.x); FMA2(acc[2][3], A23.x, B47.y);
            FMA2(acc[3][0], A23.y, B03.x); FMA2(acc[3][1], A23.y, B03.y);
            FMA2(acc[3][2], A23.y, B47.x); FMA2(acc[3][3], A23.y, B47.y);
            FMA2(acc[4][0], A45.x, B03.x); FMA2(acc[4][1], A45.x, B03.y);
            FMA2(acc[4][2], A45.x, B47.x); FMA2(acc[4][3], A45.x, B47.y);
            FMA2(acc[5][0], A45.y, B03.x); FMA2(acc[5][1], A45.y, B03.y);
            FMA2(acc[5][2], A45.y, B47.x); FMA2(acc[5][3], A45.y, B47.y);
            FMA2(acc[6][0], A67.x, B03.x); FMA2(acc[6][1], A67.x, B03.y);
            FMA2(acc[6][2], A67.x, B47.x); FMA2(acc[6][3], A67.x, B47.y);
            FMA2(acc[7][0], A67.y, B03.x); FMA2(acc[7][1], A67.y, B03.y);
            FMA2(acc[7][2], A67.y, B47.x); FMA2(acc[7][3], A67.y, B47.y);
        }
        __syncthreads();
    }
#pragma unroll
    for (int i = 0; i < 8; i++) {
        int row = mBase + ty * 8 + i;
#pragma unroll
        for (int jp = 0; jp < 4; jp += 2) {
            int col = nBase + tx * 8 + jp * 2;
            unsigned lo0, hi0, lo1, hi1;
            asm("mov.b64 {%0, %1}, %2;" : "=r"(lo0), "=r"(hi0) : "l"(acc[i][jp]));
            asm("mov.b64 {%0, %1}, %2;" : "=r"(lo1), "=r"(hi1) : "l"(acc[i][jp + 1]));
            float4 o;
            o.x = __uint_as_float(lo0) + bias[col + 0];
            o.y = __uint_as_float(hi0) + bias[col + 1];
            o.z = __uint_as_float(lo1) + bias[col + 2];
            o.w = __uint_as_float(hi1) + bias[col + 3];
            *(float4*)(C + (size_t)row * N + col) = o;
        }
    }
}

// ---------------- recurrent LSTM scan: 2 batches per CTA, shuffle-cell ----------------
// 64 CTAs: dir = blk>>5, pair bp = blk&31 -> batches b0=2bp, b0+1.
// 512 threads: u = tid>>2, q = tid&3, s = q>>1 (cell batch).
// Each thread: quarter-dots (k in [32q,32q+32)) for all 4 gates of unit u, BOTH batches.
// Weights (regs + smem) are shared across the two batches -> smem weight LDS amortized 2x.
// h buffers: per batch 4 bank-staggered copies (stride 136), batch1 base offset 552.
extern __shared__ float swq[];   // [SGQ][512][4]

__global__ __launch_bounds__(512, 1) void lstm_scan(int layer) {
    int tid = threadIdx.x;
    int dir = blockIdx.x >> 5;
    int bp = blockIdx.x & 31;
    int b0 = bp * 2;
    int seg = layer * 2 + dir;
    int u = tid >> 2, q = tid & 3;
    int s = q >> 1;

    __shared__ __align__(16) float hbuf[2][1096];  // [buf][b0: 4x136 | b1 at 552: 4x136]

    // ---- stage smem weight quads RGQ..31 ----
    {
        const float4* src = (const float4*)(g_wq + (size_t)seg * 65536 + RGQ * 2048);
        float4* dst = (float4*)swq;
        for (int j = tid; j < SGQ * 512; j += 512) dst[j] = src[j];
    }
    // ---- register weight quads 0..RGQ-1 ----
    ulonglong2 wreg[RGQ];
    {
        const float* wb = g_wq + (size_t)seg * 65536 + tid * 4;
#pragma unroll
        for (int m = 0; m < RGQ; m++) wreg[m] = *(const ulonglong2*)(wb + m * 2048);
    }
    for (int j = tid; j < 2 * 1096; j += 512) ((float*)hbuf)[j] = 0.f;
    __syncthreads();

    // z columns: gate q, unit u, batches b0 and b0+1
    const float* zc0 = g_zx + ((size_t)dir * B_ + b0) * T_ * G_ + q * 128 + u;
    const float* zc1 = zc0 + (size_t)T_ * G_;
    const int mrow = (b0 + s) * T_;
    float zp0, zp1, mpre;
    {
        int te0 = dir ? (T_ - 1) : 0;
        zp0 = zc0[(size_t)te0 * G_];
        zp1 = zc1[(size_t)te0 * G_];
        mpre = g_mask[mrow + te0];
    }
    float c_state = 0.f, hprev = 0.f;

    for (int t = 0; t < T_; t++) {
        int te = dir ? (T_ - 1 - t) : t;
        int cur = t & 1, nxt = cur ^ 1;

        float nz0 = 0.f, nz1 = 0.f, nm = 0.f;
        if (t + 1 < T_) {
            int tn = dir ? (T_ - 2 - t) : (t + 1);
            nz0 = zc0[(size_t)tn * G_];
            nz1 = zc1[(size_t)tn * G_];
            nm = g_mask[mrow + tn];
        }

        // ---- quarter-dots, streaming h by 4-float group (both batches per weight) ----
        const float* h0base = &hbuf[cur][q * 168];          // 136q + 32q
        const float* h1base = &hbuf[cur][552 + q * 168];
        unsigned long long acc0[4] = {0ull, 0ull, 0ull, 0ull};
        unsigned long long acc1[4] = {0ull, 0ull, 0ull, 0ull};
        const float* swp = swq + tid * 4;
#pragma unroll
        for (int g = 0; g < 8; g++) {
            ulonglong2 h0 = *(const ulonglong2*)(h0base + 4 * g);
            ulonglong2 h1 = *(const ulonglong2*)(h1base + 4 * g);
#pragma unroll
            for (int gate = 0; gate < 4; gate++) {
                int m = gate * 8 + g;
                ulonglong2 w;
                if (m < RGQ) w = wreg[m];
                else w = *(const ulonglong2*)(swp + (m - RGQ) * 2048);
                FMA2(acc0[gate], w.x, h0.x);
                FMA2(acc0[gate], w.y, h0.y);
                FMA2(acc1[gate], w.x, h1.x);
                FMA2(acc1[gate], w.y, h1.y);
            }
        }
        float p0 = f32x2_sum(acc0[0]);
        float p1 = f32x2_sum(acc0[1]);
        float p2 = f32x2_sum(acc0[2]);
        float p3 = f32x2_sum(acc0[3]);
        float r0 = f32x2_sum(acc1[0]);
        float r1 = f32x2_sum(acc1[1]);
        float r2 = f32x2_sum(acc1[2]);
        float r3 = f32x2_sum(acc1[3]);
        p0 += (q == 0) ? zp0 : 0.f;  r0 += (q == 0) ? zp1 : 0.f;
        p1 += (q == 1) ? zp0 : 0.f;  r1 += (q == 1) ? zp1 : 0.f;
        p2 += (q == 2) ? zp0 : 0.f;  r2 += (q == 2) ? zp1 : 0.f;
        p3 += (q == 3) ? zp0 : 0.f;  r3 += (q == 3) ? zp1 : 0.f;

        // butterfly over the 4-lane group
        p0 += __shfl_xor_sync(0xFFFFFFFFu, p0, 1);
        p1 += __shfl_xor_sync(0xFFFFFFFFu, p1, 1);
        p2 += __shfl_xor_sync(0xFFFFFFFFu, p2, 1);
        p3 += __shfl_xor_sync(0xFFFFFFFFu, p3, 1);
        r0 += __shfl_xor_sync(0xFFFFFFFFu, r0, 1);
        r1 += __shfl_xor_sync(0xFFFFFFFFu, r1, 1);
        r2 += __shfl_xor_sync(0xFFFFFFFFu, r2, 1);
        r3 += __shfl_xor_sync(0xFFFFFFFFu, r3, 1);
        p0 += __shfl_xor_sync(0xFFFFFFFFu, p0, 2);
        p1 += __shfl_xor_sync(0xFFFFFFFFu, p1, 2);
        p2 += __shfl_xor_sync(0xFFFFFFFFu, p2, 2);
        p3 += __shfl_xor_sync(0xFFFFFFFFu, p3, 2);
        r0 += __shfl_xor_sync(0xFFFFFFFFu, r0, 2);
        r1 += __shfl_xor_sync(0xFFFFFFFFu, r1, 2);
        r2 += __shfl_xor_sync(0xFFFFFFFFu, r2, 2);
        r3 += __shfl_xor_sync(0xFFFFFFFFu, r3, 2);

        // ---- cell for own batch s (2 redundant lanes per cell, identical math) ----
        float vi = s ? r0 : p0;
        float vf = s ? r1 : p1;
        float vg = s ? r2 : p2;
        float vo = s ? r3 : p3;
        float si = 1.f / (1.f + __expf(-vi));
        float sf = 1.f / (1.f + __expf(-vf));
        float so = 1.f / (1.f + __expf(-vo));
        float cn = sf * c_state + si * tanhf(vg);
        float hn = so * tanhf(cn);
        bool mm = (mpre != 0.f);
        c_state = mm ? cn : c_state;
        float hnew = mm ? hn : hprev;
        {
            int cp = (q & 1) * 2;
            float* wb2 = &hbuf[nxt][s * 552];
            wb2[cp * 136 + u] = hnew;
            wb2[(cp + 1) * 136 + u] = hnew;
        }
        if (layer == 0 && (q & 1) == 0)
            g_h1[((size_t)(b0 + s) * T_ + te) * (2 * U_) + dir * U_ + u] = hnew;
        hprev = hnew;
        zp0 = nz0; zp1 = nz1; mpre = nm;
        __syncthreads();
    }

    if (layer == 1 && (q & 1) == 0)
        g_h2[(b0 + s) * (2 * U_) + dir * U_ + u] = hprev;
}

// ---------------- head ----------------
__global__ __launch_bounds__(128) void head_kernel(
    const float* __restrict__ Wd, const float* __restrict__ bd,
    const float* __restrict__ Ws, const float* __restrict__ bs,
    float* __restrict__ out) {
    int b = blockIdx.x, u = threadIdx.x;
    float acc = bd[u];
    const float* h2 = g_h2 + b * (2 * U_);
#pragma unroll 8
    for (int j = 0; j < 2 * U_; j++) acc = fmaf(h2[j], Wd[j * U_ + u], acc);
    acc = fmaxf(acc, 0.f);
    float s = acc * Ws[u];
    __shared__ float red[128];
    red[u] = s;
    __syncthreads();
    for (int off = 64; off; off >>= 1) {
        if (u < off) red[u] += red[u + off];
        __syncthreads();
    }
    if (u == 0) out[b] = 1.f / (1.f + expf(-(red[0] + bs[0])));
}

// ---------------- launch ----------------
extern "C" void kernel_launch(void* const* d_in, const int* in_sizes, int n_in,
                              void* d_out, int out_size) {
    const float* x    = (const float*)d_in[0];
    const float* W1fi = (const float*)d_in[1];
    const float* W1fh = (const float*)d_in[2];
    const float* b1f  = (const float*)d_in[3];
    const float* W1bi = (const float*)d_in[4];
    const float* W1bh = (const float*)d_in[5];
    const float* b1b  = (const float*)d_in[6];
    const float* W2fi = (const float*)d_in[7];
    const float* W2fh = (const float*)d_in[8];
    const float* b2f  = (const float*)d_in[9];
    const float* W2bi = (const float*)d_in[10];
    const float* W2bh = (const float*)d_in[11];
    const float* b2b  = (const float*)d_in[12];
    const float* Wd   = (const float*)d_in[13];
    const float* bd   = (const float*)d_in[14];
    const float* Ws   = (const float*)d_in[15];
    const float* bs   = (const float*)d_in[16];

    const int SWB = SGQ * 2048 * 4;   // dynamic smem for weight quads
    static int attrDone = 0;
    if (!attrDone) {
        cudaFuncSetAttribute(lstm_scan, cudaFuncAttributeMaxDynamicSharedMemorySize, SWB);
        attrDone = 1;
    }

    int prepWork = B_ * T_ + 4 * G_ * U_;
    prep_kernel<<<(prepWork + 255) / 256, 256>>>(x, W1fh, W1bh, W2fh, W2bh);

    dim3 ggrid(G_ / 128, (B_ * T_) / 128);  // (4, 256)

    sgemm_bias<<<ggrid, 256>>>(x, 0, W1fi, b1f, 0, B_ * T_, G_, F_);
    sgemm_bias<<<ggrid, 256>>>(x, 0, W1bi, b1b, 1, B_ * T_, G_, F_);
    lstm_scan<<<64, 512, SWB>>>(0);

    sgemm_bias<<<ggrid, 256>>>(nullptr, 1, W2fi, b2f, 0, B_ * T_, G_, 2 * U_);
    sgemm_bias<<<ggrid, 256>>>(nullptr, 1, W2bi, b2b, 1, B_ * T_, G_, 2 * U_);
    lstm_scan<<<64, 512, SWB>>>(1);

    head_kernel<<<64, 128>>>(Wd, bd, Ws, bs, (float*)d_out);
}

// round 10
// speedup vs baseline: 1.2586x; 1.2586x over previous
#include <cuda_runtime.h>
#include <math.h>
#include <stdint.h>

#define B_ 64
#define T_ 512
#define F_ 64
#define U_ 128
#define G_ 512   // 4*U

#define RGQ 21   // weight quads (4 floats) per thread in registers
#define SGQ 11   // weight quads per thread in smem (RGQ+SGQ = 32)

// ---------------- scratch (static device memory; no allocations) ----------------
__device__ float g_mask[B_ * T_];
__device__ float g_zx[2u * B_ * T_ * G_];               // layer1 then layer2 (reused)
__device__ float g_h1[B_ * T_ * 2 * U_];
__device__ float g_h2[B_ * 2 * U_];
// packed recurrent weights, quad layout:
// g_wq[seg*65536 + (m*512 + tid)*4 + e], m = gate*8 + g, tid = u*4 + q,
// holding w[k = 32q + 4g + e][col = gate*128 + u]
__device__ float g_wq[4 * G_ * U_];

// ---------------- helpers ----------------
#define FMA2(acc, a, b) asm("fma.rn.f32x2 %0, %1, %2, %0;" : "+l"(acc) : "l"(a), "l"(b))

__device__ __forceinline__ float f32x2_sum(unsigned long long v) {
    unsigned lo, hi;
    asm("mov.b64 {%0, %1}, %2;" : "=r"(lo), "=r"(hi) : "l"(v));
    return __uint_as_float(lo) + __uint_as_float(hi);
}

// ---------------- prep: mask + weight quad-packing ----------------
__global__ void prep_kernel(const float* __restrict__ x,
                            const float* __restrict__ w1f, const float* __restrict__ w1b,
                            const float* __restrict__ w2f, const float* __restrict__ w2b) {
    int i = blockIdx.x * blockDim.x + threadIdx.x;
    if (i < B_ * T_) {
        const float4* row = (const float4*)(x + (size_t)i * F_);
        bool nz = false;
#pragma unroll
        for (int k = 0; k < F_ / 4; k++) {
            float4 v = row[k];
            nz = nz || (v.x != 0.f) || (v.y != 0.f) || (v.z != 0.f) || (v.w != 0.f);
        }
        g_mask[i] = nz ? 1.f : 0.f;
    }
    int j2 = i - B_ * T_;
    if (j2 >= 0 && j2 < 4 * G_ * U_) {
        int w = j2 >> 16;
        int r = j2 & 65535;
        int k = r >> 9;            // 0..127
        int col = r & 511;         // 0..511
        const float* src = (w == 0) ? w1f : (w == 1) ? w1b : (w == 2) ? w2f : w2b;
        int u = col & 127, gate = col >> 7;
        int q = k >> 5, g = (k >> 2) & 7, e = k & 3;
        int tid2 = u * 4 + q;
        int m = gate * 8 + g;
        g_wq[w * 65536 + (m * 512 + tid2) * 4 + e] = src[r];
    }
}

// ---------------- tiled fp32 GEMM with bias (R6/R8 proven version) ----------------
__global__ __launch_bounds__(256) void sgemm_bias(
    const float* __restrict__ Aext, int useH1,
    const float* __restrict__ W, const float* __restrict__ bias,
    int dirOff, int M, int N, int K) {
    __shared__ float As[16][132];
    __shared__ float Bs[16][128];
    const float* A = useH1 ? g_h1 : Aext;
    float* C = g_zx + (size_t)dirOff * B_ * T_ * G_;

    int tid = threadIdx.x;
    int nBase = blockIdx.x * 128;
    int mBase = blockIdx.y * 128;
    int tx = tid & 15, ty = tid >> 4;
    float acc[8][8];
#pragma unroll
    for (int i = 0; i < 8; i++)
#pragma unroll
        for (int j = 0; j < 8; j++) acc[i][j] = 0.f;

    for (int k0 = 0; k0 < K; k0 += 16) {
#pragma unroll
        for (int s = 0; s < 2; s++) {
            int slot = tid + s * 256;
            int row = slot >> 2, c4 = slot & 3;
            float4 v = *(const float4*)(A + (size_t)(mBase + row) * K + k0 + c4 * 4);
            As[c4 * 4 + 0][row] = v.x;
            As[c4 * 4 + 1][row] = v.y;
            As[c4 * 4 + 2][row] = v.z;
            As[c4 * 4 + 3][row] = v.w;
        }
#pragma unroll
        for (int s = 0; s < 2; s++) {
            int slot = tid + s * 256;
            int row = slot >> 5, c4 = slot & 31;
            *(float4*)(&Bs[row][c4 * 4]) =
                *(const float4*)(W + (size_t)(k0 + row) * N + nBase + c4 * 4);
        }
        __syncthreads();
#pragma unroll
        for (int k = 0; k < 16; k++) {
            float a[8], b[8];
            *(float4*)(a)     = *(const float4*)&As[k][ty * 8];
            *(float4*)(a + 4) = *(const float4*)&As[k][ty * 8 + 4];
            *(float4*)(b)     = *(const float4*)&Bs[k][tx * 8];
            *(float4*)(b + 4) = *(const float4*)&Bs[k][tx * 8 + 4];
#pragma unroll
            for (int i = 0; i < 8; i++)
#pragma unroll
                for (int j = 0; j < 8; j++) acc[i][j] = fmaf(a[i], b[j], acc[i][j]);
        }
        __syncthreads();
    }
#pragma unroll
    for (int i = 0; i < 8; i++) {
        int row = mBase + ty * 8 + i;
#pragma unroll
        for (int j = 0; j < 8; j += 4) {
            int col = nBase + tx * 8 + j;
            float4 o;
            o.x = acc[i][j + 0] + bias[col + 0];
            o.y = acc[i][j + 1] + bias[col + 1];
            o.z = acc[i][j + 2] + bias[col + 2];
            o.w = acc[i][j + 3] + bias[col + 3];
            *(float4*)(C + (size_t)row * N + col) = o;
        }
    }
}

// ---------------- recurrent LSTM scan: shuffle-cell, 1 CTA per sequence ----------------
// 128 CTAs: dir = blk>>6, b = blk&63. 512 threads: u = tid>>2 (unit), q = tid&3 (k-quarter).
// Each thread: quarter-dots for all 4 gates of unit u; butterfly over the 4-lane group;
// cell computed redundantly in the group; h double-buffered (4 bank-staggered copies).
// h streamed per 4-float group (no harr preload) -> freed regs hold RGQ=21 weight quads.
extern __shared__ float swq[];   // [SGQ][512][4]

__global__ __launch_bounds__(512, 1) void lstm_scan(int layer) {
    int tid = threadIdx.x;
    int dir = blockIdx.x >> 6;
    int b = blockIdx.x & 63;
    int seg = layer * 2 + dir;
    int u = tid >> 2, q = tid & 3;

    // 4 copies of h per buffer, copy q at float offset q*136 (bank-staggered)
    __shared__ __align__(16) float hbuf[2][544];

    // ---- stage smem weight quads RGQ..31 ----
    {
        const float4* src = (const float4*)(g_wq + (size_t)seg * 65536 + RGQ * 2048);
        float4* dst = (float4*)swq;
        for (int j = tid; j < SGQ * 512; j += 512) dst[j] = src[j];
    }
    // ---- register weight quads 0..RGQ-1 ----
    ulonglong2 wreg[RGQ];
    {
        const float* wb = g_wq + (size_t)seg * 65536 + tid * 4;
#pragma unroll
        for (int m = 0; m < RGQ; m++) wreg[m] = *(const ulonglong2*)(wb + m * 2048);
    }
    for (int j = tid; j < 1088; j += 512) ((float*)hbuf)[j] = 0.f;
    __syncthreads();

    // z column for this thread: gate q, unit u
    const float* zc = g_zx + ((size_t)dir * B_ + b) * T_ * G_ + q * 128 + u;
    const int mb = b * T_;
    float zpre, mpre;
    {
        int te0 = dir ? (T_ - 1) : 0;
        zpre = zc[(size_t)te0 * G_];
        mpre = g_mask[mb + te0];
    }
    float c_state = 0.f, hprev = 0.f;

    for (int t = 0; t < T_; t++) {
        int te = dir ? (T_ - 1 - t) : t;
        int cur = t & 1, nxt = cur ^ 1;

        // prefetch next step's z/mask (issued ~full step before use)
        float znext = 0.f, mnext = 0.f;
        if (t + 1 < T_) {
            int tn = dir ? (T_ - 2 - t) : (t + 1);
            znext = zc[(size_t)tn * G_];
            mnext = g_mask[mb + tn];
        }

        // ---- quarter-dots for all 4 gates, h streamed per 4-float group ----
        const float* hc = &hbuf[cur][q * 168];   // copy q, k-quarter offset 32q
        const float* swp = swq + tid * 4;
        unsigned long long acc[4] = {0ull, 0ull, 0ull, 0ull};
#pragma unroll
        for (int g = 0; g < 8; g++) {
            ulonglong2 h = *(const ulonglong2*)(hc + 4 * g);
#pragma unroll
            for (int gate = 0; gate < 4; gate++) {
                int m = gate * 8 + g;
                ulonglong2 w;
                if (m < RGQ) w = wreg[m];
                else w = *(const ulonglong2*)(swp + (m - RGQ) * 2048);
                FMA2(acc[gate], w.x, h.x);
                FMA2(acc[gate], w.y, h.y);
            }
        }
        float v0 = f32x2_sum(acc[0]);
        float v1 = f32x2_sum(acc[1]);
        float v2 = f32x2_sum(acc[2]);
        float v3 = f32x2_sum(acc[3]);
        // add z into own gate's partial (z counted exactly once per gate)
        v0 += (q == 0) ? zpre : 0.f;
        v1 += (q == 1) ? zpre : 0.f;
        v2 += (q == 2) ? zpre : 0.f;
        v3 += (q == 3) ? zpre : 0.f;

        // ---- butterfly over the 4-lane group ----
        v0 += __shfl_xor_sync(0xFFFFFFFFu, v0, 1);
        v1 += __shfl_xor_sync(0xFFFFFFFFu, v1, 1);
        v2 += __shfl_xor_sync(0xFFFFFFFFu, v2, 1);
        v3 += __shfl_xor_sync(0xFFFFFFFFu, v3, 1);
        v0 += __shfl_xor_sync(0xFFFFFFFFu, v0, 2);
        v1 += __shfl_xor_sync(0xFFFFFFFFu, v1, 2);
        v2 += __shfl_xor_sync(0xFFFFFFFFu, v2, 2);
        v3 += __shfl_xor_sync(0xFFFFFFFFu, v3, 2);

        // ---- cell (redundant in all 4 lanes; identical arithmetic) ----
        float si = 1.f / (1.f + __expf(-v0));
        float sf = 1.f / (1.f + __expf(-v1));
        float so = 1.f / (1.f + __expf(-v3));
        float cn = sf * c_state + si * tanhf(v2);
        float hn = so * tanhf(cn);
        bool mm = (mpre != 0.f);
        c_state = mm ? cn : c_state;
        float hnew = mm ? hn : hprev;
        hbuf[nxt][q * 136 + u] = hnew;   // lane q updates copy q
        if (layer == 0 && q == 0)
            g_h1[((size_t)b * T_ + te) * (2 * U_) + dir * U_ + u] = hnew;
        hprev = hnew;
        zpre = znext;
        mpre = mnext;
        __syncthreads();
    }

    if (layer == 1 && q == 0)
        g_h2[b * (2 * U_) + dir * U_ + u] = hprev;
}

// ---------------- head ----------------
__global__ __launch_bounds__(128) void head_kernel(
    const float* __restrict__ Wd, const float* __restrict__ bd,
    const float* __restrict__ Ws, const float* __restrict__ bs,
    float* __restrict__ out) {
    int b = blockIdx.x, u = threadIdx.x;
    float acc = bd[u];
    const float* h2 = g_h2 + b * (2 * U_);
#pragma unroll 8
    for (int j = 0; j < 2 * U_; j++) acc = fmaf(h2[j], Wd[j * U_ + u], acc);
    acc = fmaxf(acc, 0.f);
    float s = acc * Ws[u];
    __shared__ float red[128];
    red[u] = s;
    __syncthreads();
    for (int off = 64; off; off >>= 1) {
        if (u < off) red[u] += red[u + off];
        __syncthreads();
    }
    if (u == 0) out[b] = 1.f / (1.f + expf(-(red[0] + bs[0])));
}

// ---------------- launch ----------------
extern "C" void kernel_launch(void* const* d_in, const int* in_sizes, int n_in,
                              void* d_out, int out_size) {
    const float* x    = (const float*)d_in[0];
    const float* W1fi = (const float*)d_in[1];
    const float* W1fh = (const float*)d_in[2];
    const float* b1f  = (const float*)d_in[3];
    const float* W1bi = (const float*)d_in[4];
    const float* W1bh = (const float*)d_in[5];
    const float* b1b  = (const float*)d_in[6];
    const float* W2fi = (const float*)d_in[7];
    const float* W2fh = (const float*)d_in[8];
    const float* b2f  = (const float*)d_in[9];
    const float* W2bi = (const float*)d_in[10];
    const float* W2bh = (const float*)d_in[11];
    const float* b2b  = (const float*)d_in[12];
    const float* Wd   = (const float*)d_in[13];
    const float* bd   = (const float*)d_in[14];
    const float* Ws   = (const float*)d_in[15];
    const float* bs   = (const float*)d_in[16];

    const int SWB = SGQ * 2048 * 4;   // dynamic smem for weight quads
    static int attrDone = 0;
    if (!attrDone) {
        cudaFuncSetAttribute(lstm_scan, cudaFuncAttributeMaxDynamicSharedMemorySize, SWB);
        attrDone = 1;
    }

    int prepWork = B_ * T_ + 4 * G_ * U_;
    prep_kernel<<<(prepWork + 255) / 256, 256>>>(x, W1fh, W1bh, W2fh, W2bh);

    dim3 ggrid(G_ / 128, (B_ * T_) / 128);  // (4, 256)

    sgemm_bias<<<ggrid, 256>>>(x, 0, W1fi, b1f, 0, B_ * T_, G_, F_);
    sgemm_bias<<<ggrid, 256>>>(x, 0, W1bi, b1b, 1, B_ * T_, G_, F_);
    lstm_scan<<<128, 512, SWB>>>(0);

    sgemm_bias<<<ggrid, 256>>>(nullptr, 1, W2fi, b2f, 0, B_ * T_, G_, 2 * U_);
    sgemm_bias<<<ggrid, 256>>>(nullptr, 1, W2bi, b2b, 1, B_ * T_, G_, 2 * U_);
    lstm_scan<<<128, 512, SWB>>>(1);

    head_kernel<<<64, 128>>>(Wd, bd, Ws, bs, (float*)d_out);
}